// round 3
// baseline (speedup 1.0000x reference)
#include <cuda_runtime.h>
#include <math.h>

// Problem constants (fixed-shape problem)
#define NTOK  8192
#define DDIM  1024
#define EEXP  64
#define RRANK 64
#define GGRP  8
#define MLOC  8

#define TILE_T 32           // tokens per expert tile
#define MAX_TILES 512       // per slot: <= N/TILE_T + E = 320

// ---------------- scratch (device globals; no allocations) ----------------
__device__ int   g_eid[NTOK * 2];      // global expert id per (token, slot)
__device__ float g_gate2[NTOK * 2];    // gate per (token, slot)
__device__ int   g_cnt[2][EEXP];
__device__ int   g_off[2][EEXP];
__device__ int   g_fill[2][EEXP];
__device__ int   g_tok[2][NTOK];       // token index, grouped by expert, per slot
__device__ float g_tg[2][NTOK];        // matching gate
__device__ int   g_tiles[2][MAX_TILES];// packed: (e<<16) | tile_index_within_expert
__device__ int   g_ntiles[2];

// ---------------- init: zero counters ----------------
__global__ void init_kernel() {
    int t = threadIdx.x;
    if (t < EEXP) {
        g_cnt[0][t] = 0; g_cnt[1][t] = 0;
        g_fill[0][t] = 0; g_fill[1][t] = 0;
    }
    if (t == 0) { g_ntiles[0] = 0; g_ntiles[1] = 0; }
}

// ---------------- routing: one warp per token ----------------
// Computes group argmax, within-group top-2, softmax gate.
// Writes scratch (g_eid/g_gate2, histogram) and optional output tails.
__global__ void routing_kernel(const float* __restrict__ h,
                               const float* __restrict__ Wg,
                               const float* __restrict__ bg,
                               const float* __restrict__ Wloc,
                               float* __restrict__ o_eid,    // may be null
                               float* __restrict__ o_gate,   // may be null
                               float* __restrict__ o_grp,    // may be null
                               int n)
{
    int warp = (blockIdx.x * blockDim.x + threadIdx.x) >> 5;
    int lane = threadIdx.x & 31;
    if (warp >= n) return;

    const float* hrow = h + (size_t)warp * DDIM;

    // each lane holds h[d] for d = i*32 + lane
    float hv[32];
#pragma unroll
    for (int i = 0; i < 32; i++) hv[i] = hrow[i * 32 + lane];

    // ---- stage 1: group scores (G=8) ----
    float sg[GGRP];
#pragma unroll
    for (int g = 0; g < GGRP; g++) sg[g] = 0.f;
#pragma unroll
    for (int i = 0; i < 32; i++) {
        int d = i * 32 + lane;
        const float4* wp = (const float4*)(Wg + (size_t)d * GGRP);
        float4 wa = wp[0], wb = wp[1];
        float x = hv[i];
        sg[0] += x * wa.x; sg[1] += x * wa.y; sg[2] += x * wa.z; sg[3] += x * wa.w;
        sg[4] += x * wb.x; sg[5] += x * wb.y; sg[6] += x * wb.z; sg[7] += x * wb.w;
    }
#pragma unroll
    for (int g = 0; g < GGRP; g++) {
#pragma unroll
        for (int off = 16; off > 0; off >>= 1)
            sg[g] += __shfl_xor_sync(0xFFFFFFFFu, sg[g], off);
        sg[g] += bg[g];
    }
    // argmax, first index wins ties (matches jnp.argmax)
    int gi = 0; float best = sg[0];
#pragma unroll
    for (int g = 1; g < GGRP; g++) if (sg[g] > best) { best = sg[g]; gi = g; }

    // ---- stage 2: local scores for selected group (M=8) ----
    float sl[MLOC];
#pragma unroll
    for (int m = 0; m < MLOC; m++) sl[m] = 0.f;
    const float* wl = Wloc + (size_t)gi * DDIM * MLOC;
#pragma unroll
    for (int i = 0; i < 32; i++) {
        int d = i * 32 + lane;
        const float4* wp = (const float4*)(wl + (size_t)d * MLOC);
        float4 wa = wp[0], wb = wp[1];
        float x = hv[i];
        sl[0] += x * wa.x; sl[1] += x * wa.y; sl[2] += x * wa.z; sl[3] += x * wa.w;
        sl[4] += x * wb.x; sl[5] += x * wb.y; sl[6] += x * wb.z; sl[7] += x * wb.w;
    }
#pragma unroll
    for (int m = 0; m < MLOC; m++) {
#pragma unroll
        for (int off = 16; off > 0; off >>= 1)
            sl[m] += __shfl_xor_sync(0xFFFFFFFFu, sl[m], off);
    }
    // top-2, first-index tie rule (matches lax.top_k stability)
    int m1 = 0; float v1 = sl[0];
#pragma unroll
    for (int m = 1; m < MLOC; m++) if (sl[m] > v1) { v1 = sl[m]; m1 = m; }
    int m2 = -1; float v2 = -INFINITY;
#pragma unroll
    for (int m = 0; m < MLOC; m++) if (m != m1 && sl[m] > v2) { v2 = sl[m]; m2 = m; }

    // softmax over (v1, v2), v1 >= v2
    float e2 = expf(v2 - v1);
    float inv = 1.0f / (1.0f + e2);
    float gate0 = inv;
    float gate1 = e2 * inv;

    int eid0 = gi * MLOC + m1;
    int eid1 = gi * MLOC + m2;

    if (lane == 0) {
        g_eid[2 * warp + 0] = eid0;
        g_eid[2 * warp + 1] = eid1;
        g_gate2[2 * warp + 0] = gate0;
        g_gate2[2 * warp + 1] = gate1;
        atomicAdd(&g_cnt[0][eid0], 1);
        atomicAdd(&g_cnt[1][eid1], 1);
        if (o_eid)  { o_eid[2 * warp + 0] = (float)eid0; o_eid[2 * warp + 1] = (float)eid1; }
        if (o_gate) { o_gate[2 * warp + 0] = gate0;      o_gate[2 * warp + 1] = gate1; }
        if (o_grp)  { o_grp[warp] = (float)gi; }
    }
}

// ---------------- prefix sums + tile lists (tiny; single thread) ----------------
__global__ void prefix_kernel() {
    if (threadIdx.x != 0 || blockIdx.x != 0) return;
#pragma unroll
    for (int s = 0; s < 2; s++) {
        int acc = 0, nt = 0;
        for (int e = 0; e < EEXP; e++) {
            g_off[s][e] = acc;
            int c = g_cnt[s][e];
            acc += c;
            int t = (c + TILE_T - 1) / TILE_T;
            for (int i = 0; i < t && nt < MAX_TILES; i++)
                g_tiles[s][nt++] = (e << 16) | i;
        }
        g_ntiles[s] = nt;
    }
}

// ---------------- scatter tokens into per-expert, per-slot buckets ----------------
__global__ void scatter_kernel(int n) {
    int t = blockIdx.x * blockDim.x + threadIdx.x;
    if (t >= n) return;
#pragma unroll
    for (int j = 0; j < 2; j++) {
        int e = g_eid[2 * t + j];
        int p = g_off[j][e] + atomicAdd(&g_fill[j][e], 1);
        g_tok[j][p] = t;
        g_tg[j][p]  = g_gate2[2 * t + j];
    }
}

// ---------------- expert compute: one tile = (expert, 32 tokens) ----------------
// Phase 1: A = gate * relu(H_tile @ W1[e])   (32 x 64)
// Phase 2: out_tile = A @ W2[e]              (32 x 1024), write or accumulate.
// Thread map: tt = tid&15 -> tokens {2tt, 2tt+1}; rg = tid>>4 -> 4 columns.
template <int ACCUM>
__global__ void expert_kernel(const float* __restrict__ h,
                              const float* __restrict__ W1,
                              const float* __restrict__ W2,
                              float* __restrict__ out,
                              int slot)
{
    __shared__ float Hs[TILE_T][65];     // 32 x 64 (+pad)
    __shared__ float Ws[64 * 64];        // W1 k-tile, reused for W2 c-tile
    __shared__ float As[TILE_T][65];
    __shared__ int   tok_s[TILE_T];
    __shared__ float gsc[TILE_T];

    int tid = threadIdx.x;
    int tt = tid & 15, rg = tid >> 4;
    int t0 = 2 * tt, t1 = t0 + 1;
    int r0 = rg * 4;

    int ntiles = g_ntiles[slot];
    for (int tile = blockIdx.x; tile < ntiles; tile += gridDim.x) {
        int desc = g_tiles[slot][tile];
        int e  = desc >> 16;
        int ti = desc & 0xFFFF;
        int cnt_e = g_cnt[slot][e];
        int base  = g_off[slot][e] + ti * TILE_T;
        int nv = cnt_e - ti * TILE_T;
        if (nv > TILE_T) nv = TILE_T;

        if (tid < TILE_T) {
            int rr = tid < nv ? tid : (nv - 1);   // clamp; invalid rows masked at store
            tok_s[tid] = g_tok[slot][base + rr];
            gsc[tid]   = g_tg[slot][base + rr];
        }
        __syncthreads();

        // ---------------- phase 1: A = gate * relu(H @ W1[e]) ----------------
        float a0[4] = {0.f, 0.f, 0.f, 0.f};
        float a1[4] = {0.f, 0.f, 0.f, 0.f};
        const float* W1e = W1 + (size_t)e * DDIM * RRANK;

        for (int kt = 0; kt < DDIM / 64; kt++) {
            int k0 = kt * 64;
#pragma unroll
            for (int i = 0; i < 8; i++) {          // 32x64 H tile
                int lin = tid + i * 256;
                int row = lin >> 6, col = lin & 63;
                Hs[row][col] = h[(size_t)tok_s[row] * DDIM + k0 + col];
            }
#pragma unroll
            for (int i = 0; i < 16; i++) {         // 64x64 W1 tile (lin == row*64+col)
                int lin = tid + i * 256;
                int row = lin >> 6;
                Ws[lin] = W1e[(size_t)(k0 + row) * RRANK + (lin & 63)];
            }
            __syncthreads();
#pragma unroll
            for (int kk = 0; kk < 64; kk++) {
                float h0 = Hs[t0][kk], h1 = Hs[t1][kk];
                float4 w = *(const float4*)&Ws[kk * 64 + r0];
                a0[0] += h0 * w.x; a0[1] += h0 * w.y; a0[2] += h0 * w.z; a0[3] += h0 * w.w;
                a1[0] += h1 * w.x; a1[1] += h1 * w.y; a1[2] += h1 * w.z; a1[3] += h1 * w.w;
            }
            __syncthreads();
        }

        float gt0 = gsc[t0], gt1 = gsc[t1];
#pragma unroll
        for (int j = 0; j < 4; j++) {
            As[t0][r0 + j] = fmaxf(a0[j], 0.f) * gt0;
            As[t1][r0 + j] = fmaxf(a1[j], 0.f) * gt1;
        }
        __syncthreads();

        // ---------------- phase 2: out = A @ W2[e] ----------------
        const float* W2e = W2 + (size_t)e * RRANK * DDIM;
        bool v0 = (t0 < nv), v1 = (t1 < nv);
        size_t ob0 = (size_t)tok_s[t0] * DDIM;
        size_t ob1 = (size_t)tok_s[t1] * DDIM;

        for (int ct = 0; ct < DDIM / 64; ct++) {
            int c0 = ct * 64;
#pragma unroll
            for (int i = 0; i < 16; i++) {         // 64x64 W2 tile
                int lin = tid + i * 256;
                int row = lin >> 6;
                Ws[lin] = W2e[(size_t)row * DDIM + c0 + (lin & 63)];
            }
            __syncthreads();

            float o0[4] = {0.f, 0.f, 0.f, 0.f};
            float o1[4] = {0.f, 0.f, 0.f, 0.f};
#pragma unroll
            for (int r = 0; r < RRANK; r++) {
                float x0 = As[t0][r], x1 = As[t1][r];
                float4 w = *(const float4*)&Ws[r * 64 + r0];
                o0[0] += x0 * w.x; o0[1] += x0 * w.y; o0[2] += x0 * w.z; o0[3] += x0 * w.w;
                o1[0] += x1 * w.x; o1[1] += x1 * w.y; o1[2] += x1 * w.z; o1[3] += x1 * w.w;
            }
            int c = c0 + r0;
            if (ACCUM) {
                if (v0) {
                    float4* p = (float4*)&out[ob0 + c];
                    float4 cur = *p;
                    cur.x += o0[0]; cur.y += o0[1]; cur.z += o0[2]; cur.w += o0[3];
                    *p = cur;
                }
                if (v1) {
                    float4* p = (float4*)&out[ob1 + c];
                    float4 cur = *p;
                    cur.x += o1[0]; cur.y += o1[1]; cur.z += o1[2]; cur.w += o1[3];
                    *p = cur;
                }
            } else {
                if (v0) *(float4*)&out[ob0 + c] = make_float4(o0[0], o0[1], o0[2], o0[3]);
                if (v1) *(float4*)&out[ob1 + c] = make_float4(o1[0], o1[1], o1[2], o1[3]);
            }
            __syncthreads();
        }
        // loop-end barrier above also protects tok_s/gsc reuse next tile
    }
}

// ---------------- launch ----------------
extern "C" void kernel_launch(void* const* d_in, const int* in_sizes, int n_in,
                              void* d_out, int out_size)
{
    const float* h    = (const float*)d_in[0];
    const float* Wg   = (const float*)d_in[1];
    const float* bg   = (const float*)d_in[2];
    const float* Wloc = (const float*)d_in[3];
    const float* W1   = (const float*)d_in[4];
    const float* W2   = (const float*)d_in[5];

    int n = in_sizes[0] / DDIM;                 // 8192
    if (n > NTOK) n = NTOK;

    float* out = (float*)d_out;

    // Optional concatenated tail outputs: out(N*D), expert_ids(2N), gate(2N), group_idx(N)
    size_t need = (size_t)n * DDIM + 5 * (size_t)n;
    float* o_eid  = nullptr;
    float* o_gate = nullptr;
    float* o_grp  = nullptr;
    if ((size_t)out_size >= need) {
        o_eid  = out + (size_t)n * DDIM;
        o_gate = o_eid + 2 * (size_t)n;
        o_grp  = o_gate + 2 * (size_t)n;
    }

    init_kernel<<<1, 128>>>();
    routing_kernel<<<(n + 7) / 8, 256>>>(h, Wg, bg, Wloc, o_eid, o_gate, o_grp, n);
    prefix_kernel<<<1, 32>>>();
    scatter_kernel<<<(n + 255) / 256, 256>>>(n);
    // slot 0 (top-1 experts): disjoint token rows -> plain writes cover all of out
    expert_kernel<0><<<512, 256>>>(h, W1, W2, out, 0);
    // slot 1 (top-2 experts): disjoint token rows -> non-atomic accumulate
    expert_kernel<1><<<512, 256>>>(h, W1, W2, out, 1);
}

// round 4
// speedup vs baseline: 1.0069x; 1.0069x over previous
#include <cuda_runtime.h>
#include <math.h>

// Problem constants (fixed-shape problem)
#define NTOK  8192
#define DDIM  1024
#define EEXP  64
#define RRANK 64
#define GGRP  8
#define MLOC  8

#define TILE_T 32           // tokens per expert tile
#define MAX_TILES 512       // per slot: <= N/TILE_T + E = 320

// ---------------- scratch (device globals; no allocations) ----------------
__device__ int   g_eid[NTOK * 2];      // global expert id per (token, slot)
__device__ float g_gate2[NTOK * 2];    // gate per (token, slot)
__device__ int   g_cnt[2][EEXP];
__device__ int   g_off[2][EEXP];
__device__ int   g_fill[2][EEXP];
__device__ int   g_tok[2][NTOK];       // token index, grouped by expert, per slot
__device__ float g_tg[2][NTOK];        // matching gate
__device__ int   g_tiles[2][MAX_TILES];// packed: (e<<16) | tile_index_within_expert
__device__ int   g_ntiles[2];

// ---------------- init: zero counters ----------------
__global__ void init_kernel() {
    int t = threadIdx.x;
    if (t < EEXP) {
        g_cnt[0][t] = 0; g_cnt[1][t] = 0;
        g_fill[0][t] = 0; g_fill[1][t] = 0;
    }
    if (t == 0) { g_ntiles[0] = 0; g_ntiles[1] = 0; }
}

// ---------------- routing: one warp per token ----------------
// Computes group argmax, within-group top-2, softmax gate.
// Writes scratch (g_eid/g_gate2, histogram) and optional output tails.
__global__ void routing_kernel(const float* __restrict__ h,
                               const float* __restrict__ Wg,
                               const float* __restrict__ bg,
                               const float* __restrict__ Wloc,
                               float* __restrict__ o_eid,    // may be null
                               float* __restrict__ o_gate,   // may be null
                               float* __restrict__ o_grp,    // may be null
                               int n)
{
    int warp = (blockIdx.x * blockDim.x + threadIdx.x) >> 5;
    int lane = threadIdx.x & 31;
    if (warp >= n) return;

    const float* hrow = h + (size_t)warp * DDIM;

    // each lane holds h[d] for d = i*32 + lane
    float hv[32];
#pragma unroll
    for (int i = 0; i < 32; i++) hv[i] = hrow[i * 32 + lane];

    // ---- stage 1: group scores (G=8) ----
    float sg[GGRP];
#pragma unroll
    for (int g = 0; g < GGRP; g++) sg[g] = 0.f;
#pragma unroll
    for (int i = 0; i < 32; i++) {
        int d = i * 32 + lane;
        const float4* wp = (const float4*)(Wg + (size_t)d * GGRP);
        float4 wa = wp[0], wb = wp[1];
        float x = hv[i];
        sg[0] += x * wa.x; sg[1] += x * wa.y; sg[2] += x * wa.z; sg[3] += x * wa.w;
        sg[4] += x * wb.x; sg[5] += x * wb.y; sg[6] += x * wb.z; sg[7] += x * wb.w;
    }
#pragma unroll
    for (int g = 0; g < GGRP; g++) {
#pragma unroll
        for (int off = 16; off > 0; off >>= 1)
            sg[g] += __shfl_xor_sync(0xFFFFFFFFu, sg[g], off);
        sg[g] += bg[g];
    }
    // argmax, first index wins ties (matches jnp.argmax)
    int gi = 0; float best = sg[0];
#pragma unroll
    for (int g = 1; g < GGRP; g++) if (sg[g] > best) { best = sg[g]; gi = g; }

    // ---- stage 2: local scores for selected group (M=8) ----
    float sl[MLOC];
#pragma unroll
    for (int m = 0; m < MLOC; m++) sl[m] = 0.f;
    const float* wl = Wloc + (size_t)gi * DDIM * MLOC;
#pragma unroll
    for (int i = 0; i < 32; i++) {
        int d = i * 32 + lane;
        const float4* wp = (const float4*)(wl + (size_t)d * MLOC);
        float4 wa = wp[0], wb = wp[1];
        float x = hv[i];
        sl[0] += x * wa.x; sl[1] += x * wa.y; sl[2] += x * wa.z; sl[3] += x * wa.w;
        sl[4] += x * wb.x; sl[5] += x * wb.y; sl[6] += x * wb.z; sl[7] += x * wb.w;
    }
#pragma unroll
    for (int m = 0; m < MLOC; m++) {
#pragma unroll
        for (int off = 16; off > 0; off >>= 1)
            sl[m] += __shfl_xor_sync(0xFFFFFFFFu, sl[m], off);
    }
    // top-2, first-index tie rule (matches lax.top_k stability)
    int m1 = 0; float v1 = sl[0];
#pragma unroll
    for (int m = 1; m < MLOC; m++) if (sl[m] > v1) { v1 = sl[m]; m1 = m; }
    int m2 = -1; float v2 = -INFINITY;
#pragma unroll
    for (int m = 0; m < MLOC; m++) if (m != m1 && sl[m] > v2) { v2 = sl[m]; m2 = m; }

    // softmax over (v1, v2), v1 >= v2
    float e2 = expf(v2 - v1);
    float inv = 1.0f / (1.0f + e2);
    float gate0 = inv;
    float gate1 = e2 * inv;

    int eid0 = gi * MLOC + m1;
    int eid1 = gi * MLOC + m2;

    if (lane == 0) {
        g_eid[2 * warp + 0] = eid0;
        g_eid[2 * warp + 1] = eid1;
        g_gate2[2 * warp + 0] = gate0;
        g_gate2[2 * warp + 1] = gate1;
        atomicAdd(&g_cnt[0][eid0], 1);
        atomicAdd(&g_cnt[1][eid1], 1);
        if (o_eid)  { o_eid[2 * warp + 0] = (float)eid0; o_eid[2 * warp + 1] = (float)eid1; }
        if (o_gate) { o_gate[2 * warp + 0] = gate0;      o_gate[2 * warp + 1] = gate1; }
        if (o_grp)  { o_grp[warp] = (float)gi; }
    }
}

// ---------------- prefix sums + tile lists (tiny; single thread) ----------------
__global__ void prefix_kernel() {
    if (threadIdx.x != 0 || blockIdx.x != 0) return;
#pragma unroll
    for (int s = 0; s < 2; s++) {
        int acc = 0, nt = 0;
        for (int e = 0; e < EEXP; e++) {
            g_off[s][e] = acc;
            int c = g_cnt[s][e];
            acc += c;
            int t = (c + TILE_T - 1) / TILE_T;
            for (int i = 0; i < t && nt < MAX_TILES; i++)
                g_tiles[s][nt++] = (e << 16) | i;
        }
        g_ntiles[s] = nt;
    }
}

// ---------------- scatter tokens into per-expert, per-slot buckets ----------------
__global__ void scatter_kernel(int n) {
    int t = blockIdx.x * blockDim.x + threadIdx.x;
    if (t >= n) return;
#pragma unroll
    for (int j = 0; j < 2; j++) {
        int e = g_eid[2 * t + j];
        int p = g_off[j][e] + atomicAdd(&g_fill[j][e], 1);
        g_tok[j][p] = t;
        g_tg[j][p]  = g_gate2[2 * t + j];
    }
}

// ---------------- expert compute: one tile = (expert, 32 tokens) ----------------
// Phase 1: A = gate * relu(H_tile @ W1[e])   (32 x 64)
// Phase 2: out_tile = A @ W2[e]              (32 x 1024), write or accumulate.
// Thread map: tt = tid&15 -> tokens {2tt, 2tt+1}; rg = tid>>4 -> 4 columns.
template <int ACCUM>
__global__ void expert_kernel(const float* __restrict__ h,
                              const float* __restrict__ W1,
                              const float* __restrict__ W2,
                              float* __restrict__ out,
                              int slot)
{
    __shared__ float Hs[TILE_T][65];     // 32 x 64 (+pad)
    __shared__ float Ws[64 * 64];        // W1 k-tile, reused for W2 c-tile
    __shared__ float As[TILE_T][65];
    __shared__ int   tok_s[TILE_T];
    __shared__ float gsc[TILE_T];

    int tid = threadIdx.x;
    int tt = tid & 15, rg = tid >> 4;
    int t0 = 2 * tt, t1 = t0 + 1;
    int r0 = rg * 4;

    int ntiles = g_ntiles[slot];
    for (int tile = blockIdx.x; tile < ntiles; tile += gridDim.x) {
        int desc = g_tiles[slot][tile];
        int e  = desc >> 16;
        int ti = desc & 0xFFFF;
        int cnt_e = g_cnt[slot][e];
        int base  = g_off[slot][e] + ti * TILE_T;
        int nv = cnt_e - ti * TILE_T;
        if (nv > TILE_T) nv = TILE_T;

        if (tid < TILE_T) {
            int rr = tid < nv ? tid : (nv - 1);   // clamp; invalid rows masked at store
            tok_s[tid] = g_tok[slot][base + rr];
            gsc[tid]   = g_tg[slot][base + rr];
        }
        __syncthreads();

        // ---------------- phase 1: A = gate * relu(H @ W1[e]) ----------------
        float a0[4] = {0.f, 0.f, 0.f, 0.f};
        float a1[4] = {0.f, 0.f, 0.f, 0.f};
        const float* W1e = W1 + (size_t)e * DDIM * RRANK;

        for (int kt = 0; kt < DDIM / 64; kt++) {
            int k0 = kt * 64;
#pragma unroll
            for (int i = 0; i < 8; i++) {          // 32x64 H tile
                int lin = tid + i * 256;
                int row = lin >> 6, col = lin & 63;
                Hs[row][col] = h[(size_t)tok_s[row] * DDIM + k0 + col];
            }
#pragma unroll
            for (int i = 0; i < 16; i++) {         // 64x64 W1 tile (lin == row*64+col)
                int lin = tid + i * 256;
                int row = lin >> 6;
                Ws[lin] = W1e[(size_t)(k0 + row) * RRANK + (lin & 63)];
            }
            __syncthreads();
#pragma unroll
            for (int kk = 0; kk < 64; kk++) {
                float h0 = Hs[t0][kk], h1 = Hs[t1][kk];
                float4 w = *(const float4*)&Ws[kk * 64 + r0];
                a0[0] += h0 * w.x; a0[1] += h0 * w.y; a0[2] += h0 * w.z; a0[3] += h0 * w.w;
                a1[0] += h1 * w.x; a1[1] += h1 * w.y; a1[2] += h1 * w.z; a1[3] += h1 * w.w;
            }
            __syncthreads();
        }

        float gt0 = gsc[t0], gt1 = gsc[t1];
#pragma unroll
        for (int j = 0; j < 4; j++) {
            As[t0][r0 + j] = fmaxf(a0[j], 0.f) * gt0;
            As[t1][r0 + j] = fmaxf(a1[j], 0.f) * gt1;
        }
        __syncthreads();

        // ---------------- phase 2: out = A @ W2[e] ----------------
        const float* W2e = W2 + (size_t)e * RRANK * DDIM;
        bool v0 = (t0 < nv), v1 = (t1 < nv);
        size_t ob0 = (size_t)tok_s[t0] * DDIM;
        size_t ob1 = (size_t)tok_s[t1] * DDIM;

        for (int ct = 0; ct < DDIM / 64; ct++) {
            int c0 = ct * 64;
#pragma unroll
            for (int i = 0; i < 16; i++) {         // 64x64 W2 tile
                int lin = tid + i * 256;
                int row = lin >> 6;
                Ws[lin] = W2e[(size_t)row * DDIM + c0 + (lin & 63)];
            }
            __syncthreads();

            float o0[4] = {0.f, 0.f, 0.f, 0.f};
            float o1[4] = {0.f, 0.f, 0.f, 0.f};
#pragma unroll
            for (int r = 0; r < RRANK; r++) {
                float x0 = As[t0][r], x1 = As[t1][r];
                float4 w = *(const float4*)&Ws[r * 64 + r0];
                o0[0] += x0 * w.x; o0[1] += x0 * w.y; o0[2] += x0 * w.z; o0[3] += x0 * w.w;
                o1[0] += x1 * w.x; o1[1] += x1 * w.y; o1[2] += x1 * w.z; o1[3] += x1 * w.w;
            }
            int c = c0 + r0;
            if (ACCUM) {
                if (v0) {
                    float4* p = (float4*)&out[ob0 + c];
                    float4 cur = *p;
                    cur.x += o0[0]; cur.y += o0[1]; cur.z += o0[2]; cur.w += o0[3];
                    *p = cur;
                }
                if (v1) {
                    float4* p = (float4*)&out[ob1 + c];
                    float4 cur = *p;
                    cur.x += o1[0]; cur.y += o1[1]; cur.z += o1[2]; cur.w += o1[3];
                    *p = cur;
                }
            } else {
                if (v0) *(float4*)&out[ob0 + c] = make_float4(o0[0], o0[1], o0[2], o0[3]);
                if (v1) *(float4*)&out[ob1 + c] = make_float4(o1[0], o1[1], o1[2], o1[3]);
            }
            __syncthreads();
        }
        // loop-end barrier above also protects tok_s/gsc reuse next tile
    }
}

// ---------------- launch ----------------
extern "C" void kernel_launch(void* const* d_in, const int* in_sizes, int n_in,
                              void* d_out, int out_size)
{
    const float* h    = (const float*)d_in[0];
    const float* Wg   = (const float*)d_in[1];
    const float* bg   = (const float*)d_in[2];
    const float* Wloc = (const float*)d_in[3];
    const float* W1   = (const float*)d_in[4];
    const float* W2   = (const float*)d_in[5];

    int n = in_sizes[0] / DDIM;                 // 8192
    if (n > NTOK) n = NTOK;

    float* out = (float*)d_out;

    // Optional concatenated tail outputs: out(N*D), expert_ids(2N), gate(2N), group_idx(N)
    size_t need = (size_t)n * DDIM + 5 * (size_t)n;
    float* o_eid  = nullptr;
    float* o_gate = nullptr;
    float* o_grp  = nullptr;
    if ((size_t)out_size >= need) {
        o_eid  = out + (size_t)n * DDIM;
        o_gate = o_eid + 2 * (size_t)n;
        o_grp  = o_gate + 2 * (size_t)n;
    }

    init_kernel<<<1, 128>>>();
    routing_kernel<<<(n + 7) / 8, 256>>>(h, Wg, bg, Wloc, o_eid, o_gate, o_grp, n);
    prefix_kernel<<<1, 32>>>();
    scatter_kernel<<<(n + 255) / 256, 256>>>(n);
    // slot 0 (top-1 experts): disjoint token rows -> plain writes cover all of out
    expert_kernel<0><<<512, 256>>>(h, W1, W2, out, 0);
    // slot 1 (top-2 experts): disjoint token rows -> non-atomic accumulate
    expert_kernel<1><<<512, 256>>>(h, W1, W2, out, 1);
}

// round 5
// speedup vs baseline: 1.0130x; 1.0061x over previous
#include <cuda_runtime.h>
#include <math.h>

// Problem constants (fixed-shape problem)
#define NTOK  8192
#define DDIM  1024
#define EEXP  64
#define RRANK 64
#define GGRP  8
#define MLOC  8

#define TILE_T 32           // tokens per expert tile
#define MAX_TILES 512       // per slot: <= N/TILE_T + E = 320

// ---------------- scratch (device globals; no allocations) ----------------
__device__ int   g_eid[NTOK * 2];      // global expert id per (token, slot)
__device__ float g_gate2[NTOK * 2];    // gate per (token, slot)
__device__ int   g_cnt[2][EEXP];
__device__ int   g_off[2][EEXP];
__device__ int   g_fill[2][EEXP];
__device__ int   g_tok[2][NTOK];       // token index, grouped by expert, per slot
__device__ float g_tg[2][NTOK];        // matching gate
__device__ int   g_tiles[2][MAX_TILES];// packed: (e<<16) | tile_index_within_expert
__device__ int   g_ntiles[2];

// ---------------- init: zero counters ----------------
__global__ void init_kernel() {
    int t = threadIdx.x;
    if (t < EEXP) {
        g_cnt[0][t] = 0; g_cnt[1][t] = 0;
        g_fill[0][t] = 0; g_fill[1][t] = 0;
    }
    if (t == 0) { g_ntiles[0] = 0; g_ntiles[1] = 0; }
}

// ---------------- routing: one warp per token ----------------
// Computes group argmax, within-group top-2, softmax gate.
// Writes scratch (g_eid/g_gate2, histogram) and optional output tails.
__global__ void routing_kernel(const float* __restrict__ h,
                               const float* __restrict__ Wg,
                               const float* __restrict__ bg,
                               const float* __restrict__ Wloc,
                               float* __restrict__ o_eid,    // may be null
                               float* __restrict__ o_gate,   // may be null
                               float* __restrict__ o_grp,    // may be null
                               int n)
{
    int warp = (blockIdx.x * blockDim.x + threadIdx.x) >> 5;
    int lane = threadIdx.x & 31;
    if (warp >= n) return;

    const float* hrow = h + (size_t)warp * DDIM;

    // each lane holds h[d] for d = i*32 + lane
    float hv[32];
#pragma unroll
    for (int i = 0; i < 32; i++) hv[i] = hrow[i * 32 + lane];

    // ---- stage 1: group scores (G=8) ----
    float sg[GGRP];
#pragma unroll
    for (int g = 0; g < GGRP; g++) sg[g] = 0.f;
#pragma unroll
    for (int i = 0; i < 32; i++) {
        int d = i * 32 + lane;
        const float4* wp = (const float4*)(Wg + (size_t)d * GGRP);
        float4 wa = wp[0], wb = wp[1];
        float x = hv[i];
        sg[0] += x * wa.x; sg[1] += x * wa.y; sg[2] += x * wa.z; sg[3] += x * wa.w;
        sg[4] += x * wb.x; sg[5] += x * wb.y; sg[6] += x * wb.z; sg[7] += x * wb.w;
    }
#pragma unroll
    for (int g = 0; g < GGRP; g++) {
#pragma unroll
        for (int off = 16; off > 0; off >>= 1)
            sg[g] += __shfl_xor_sync(0xFFFFFFFFu, sg[g], off);
        sg[g] += bg[g];
    }
    // argmax, first index wins ties (matches jnp.argmax)
    int gi = 0; float best = sg[0];
#pragma unroll
    for (int g = 1; g < GGRP; g++) if (sg[g] > best) { best = sg[g]; gi = g; }

    // ---- stage 2: local scores for selected group (M=8) ----
    float sl[MLOC];
#pragma unroll
    for (int m = 0; m < MLOC; m++) sl[m] = 0.f;
    const float* wl = Wloc + (size_t)gi * DDIM * MLOC;
#pragma unroll
    for (int i = 0; i < 32; i++) {
        int d = i * 32 + lane;
        const float4* wp = (const float4*)(wl + (size_t)d * MLOC);
        float4 wa = wp[0], wb = wp[1];
        float x = hv[i];
        sl[0] += x * wa.x; sl[1] += x * wa.y; sl[2] += x * wa.z; sl[3] += x * wa.w;
        sl[4] += x * wb.x; sl[5] += x * wb.y; sl[6] += x * wb.z; sl[7] += x * wb.w;
    }
#pragma unroll
    for (int m = 0; m < MLOC; m++) {
#pragma unroll
        for (int off = 16; off > 0; off >>= 1)
            sl[m] += __shfl_xor_sync(0xFFFFFFFFu, sl[m], off);
    }
    // top-2, first-index tie rule (matches lax.top_k stability)
    int m1 = 0; float v1 = sl[0];
#pragma unroll
    for (int m = 1; m < MLOC; m++) if (sl[m] > v1) { v1 = sl[m]; m1 = m; }
    int m2 = -1; float v2 = -INFINITY;
#pragma unroll
    for (int m = 0; m < MLOC; m++) if (m != m1 && sl[m] > v2) { v2 = sl[m]; m2 = m; }

    // softmax over (v1, v2), v1 >= v2
    float e2 = expf(v2 - v1);
    float inv = 1.0f / (1.0f + e2);
    float gate0 = inv;
    float gate1 = e2 * inv;

    int eid0 = gi * MLOC + m1;
    int eid1 = gi * MLOC + m2;

    if (lane == 0) {
        g_eid[2 * warp + 0] = eid0;
        g_eid[2 * warp + 1] = eid1;
        g_gate2[2 * warp + 0] = gate0;
        g_gate2[2 * warp + 1] = gate1;
        atomicAdd(&g_cnt[0][eid0], 1);
        atomicAdd(&g_cnt[1][eid1], 1);
        if (o_eid)  { o_eid[2 * warp + 0] = (float)eid0; o_eid[2 * warp + 1] = (float)eid1; }
        if (o_gate) { o_gate[2 * warp + 0] = gate0;      o_gate[2 * warp + 1] = gate1; }
        if (o_grp)  { o_grp[warp] = (float)gi; }
    }
}

// ---------------- prefix sums + tile lists (tiny; single thread) ----------------
__global__ void prefix_kernel() {
    if (threadIdx.x != 0 || blockIdx.x != 0) return;
#pragma unroll
    for (int s = 0; s < 2; s++) {
        int acc = 0, nt = 0;
        for (int e = 0; e < EEXP; e++) {
            g_off[s][e] = acc;
            int c = g_cnt[s][e];
            acc += c;
            int t = (c + TILE_T - 1) / TILE_T;
            for (int i = 0; i < t && nt < MAX_TILES; i++)
                g_tiles[s][nt++] = (e << 16) | i;
        }
        g_ntiles[s] = nt;
    }
}

// ---------------- scatter tokens into per-expert, per-slot buckets ----------------
__global__ void scatter_kernel(int n) {
    int t = blockIdx.x * blockDim.x + threadIdx.x;
    if (t >= n) return;
#pragma unroll
    for (int j = 0; j < 2; j++) {
        int e = g_eid[2 * t + j];
        int p = g_off[j][e] + atomicAdd(&g_fill[j][e], 1);
        g_tok[j][p] = t;
        g_tg[j][p]  = g_gate2[2 * t + j];
    }
}

// ---------------- expert compute: one tile = (expert, 32 tokens) ----------------
// Phase 1: A = gate * relu(H_tile @ W1[e])   (32 x 64)
// Phase 2: out_tile = A @ W2[e]              (32 x 1024), write or accumulate.
// Thread map: tt = tid&15 -> tokens {2tt, 2tt+1}; rg = tid>>4 -> 4 columns.
template <int ACCUM>
__global__ void expert_kernel(const float* __restrict__ h,
                              const float* __restrict__ W1,
                              const float* __restrict__ W2,
                              float* __restrict__ out,
                              int slot)
{
    __shared__ float Hs[TILE_T][65];     // 32 x 64 (+pad)
    __shared__ float Ws[64 * 64];        // W1 k-tile, reused for W2 c-tile
    __shared__ float As[TILE_T][65];
    __shared__ int   tok_s[TILE_T];
    __shared__ float gsc[TILE_T];

    int tid = threadIdx.x;
    int tt = tid & 15, rg = tid >> 4;
    int t0 = 2 * tt, t1 = t0 + 1;
    int r0 = rg * 4;

    int ntiles = g_ntiles[slot];
    for (int tile = blockIdx.x; tile < ntiles; tile += gridDim.x) {
        int desc = g_tiles[slot][tile];
        int e  = desc >> 16;
        int ti = desc & 0xFFFF;
        int cnt_e = g_cnt[slot][e];
        int base  = g_off[slot][e] + ti * TILE_T;
        int nv = cnt_e - ti * TILE_T;
        if (nv > TILE_T) nv = TILE_T;

        if (tid < TILE_T) {
            int rr = tid < nv ? tid : (nv - 1);   // clamp; invalid rows masked at store
            tok_s[tid] = g_tok[slot][base + rr];
            gsc[tid]   = g_tg[slot][base + rr];
        }
        __syncthreads();

        // ---------------- phase 1: A = gate * relu(H @ W1[e]) ----------------
        float a0[4] = {0.f, 0.f, 0.f, 0.f};
        float a1[4] = {0.f, 0.f, 0.f, 0.f};
        const float* W1e = W1 + (size_t)e * DDIM * RRANK;

        for (int kt = 0; kt < DDIM / 64; kt++) {
            int k0 = kt * 64;
#pragma unroll
            for (int i = 0; i < 8; i++) {          // 32x64 H tile
                int lin = tid + i * 256;
                int row = lin >> 6, col = lin & 63;
                Hs[row][col] = h[(size_t)tok_s[row] * DDIM + k0 + col];
            }
#pragma unroll
            for (int i = 0; i < 16; i++) {         // 64x64 W1 tile (lin == row*64+col)
                int lin = tid + i * 256;
                int row = lin >> 6;
                Ws[lin] = W1e[(size_t)(k0 + row) * RRANK + (lin & 63)];
            }
            __syncthreads();
#pragma unroll
            for (int kk = 0; kk < 64; kk++) {
                float h0 = Hs[t0][kk], h1 = Hs[t1][kk];
                float4 w = *(const float4*)&Ws[kk * 64 + r0];
                a0[0] += h0 * w.x; a0[1] += h0 * w.y; a0[2] += h0 * w.z; a0[3] += h0 * w.w;
                a1[0] += h1 * w.x; a1[1] += h1 * w.y; a1[2] += h1 * w.z; a1[3] += h1 * w.w;
            }
            __syncthreads();
        }

        float gt0 = gsc[t0], gt1 = gsc[t1];
#pragma unroll
        for (int j = 0; j < 4; j++) {
            As[t0][r0 + j] = fmaxf(a0[j], 0.f) * gt0;
            As[t1][r0 + j] = fmaxf(a1[j], 0.f) * gt1;
        }
        __syncthreads();

        // ---------------- phase 2: out = A @ W2[e] ----------------
        const float* W2e = W2 + (size_t)e * RRANK * DDIM;
        bool v0 = (t0 < nv), v1 = (t1 < nv);
        size_t ob0 = (size_t)tok_s[t0] * DDIM;
        size_t ob1 = (size_t)tok_s[t1] * DDIM;

        for (int ct = 0; ct < DDIM / 64; ct++) {
            int c0 = ct * 64;
#pragma unroll
            for (int i = 0; i < 16; i++) {         // 64x64 W2 tile
                int lin = tid + i * 256;
                int row = lin >> 6;
                Ws[lin] = W2e[(size_t)row * DDIM + c0 + (lin & 63)];
            }
            __syncthreads();

            float o0[4] = {0.f, 0.f, 0.f, 0.f};
            float o1[4] = {0.f, 0.f, 0.f, 0.f};
#pragma unroll
            for (int r = 0; r < RRANK; r++) {
                float x0 = As[t0][r], x1 = As[t1][r];
                float4 w = *(const float4*)&Ws[r * 64 + r0];
                o0[0] += x0 * w.x; o0[1] += x0 * w.y; o0[2] += x0 * w.z; o0[3] += x0 * w.w;
                o1[0] += x1 * w.x; o1[1] += x1 * w.y; o1[2] += x1 * w.z; o1[3] += x1 * w.w;
            }
            int c = c0 + r0;
            if (ACCUM) {
                if (v0) {
                    float4* p = (float4*)&out[ob0 + c];
                    float4 cur = *p;
                    cur.x += o0[0]; cur.y += o0[1]; cur.z += o0[2]; cur.w += o0[3];
                    *p = cur;
                }
                if (v1) {
                    float4* p = (float4*)&out[ob1 + c];
                    float4 cur = *p;
                    cur.x += o1[0]; cur.y += o1[1]; cur.z += o1[2]; cur.w += o1[3];
                    *p = cur;
                }
            } else {
                if (v0) *(float4*)&out[ob0 + c] = make_float4(o0[0], o0[1], o0[2], o0[3]);
                if (v1) *(float4*)&out[ob1 + c] = make_float4(o1[0], o1[1], o1[2], o1[3]);
            }
            __syncthreads();
        }
        // loop-end barrier above also protects tok_s/gsc reuse next tile
    }
}

// ---------------- launch ----------------
extern "C" void kernel_launch(void* const* d_in, const int* in_sizes, int n_in,
                              void* d_out, int out_size)
{
    const float* h    = (const float*)d_in[0];
    const float* Wg   = (const float*)d_in[1];
    const float* bg   = (const float*)d_in[2];
    const float* Wloc = (const float*)d_in[3];
    const float* W1   = (const float*)d_in[4];
    const float* W2   = (const float*)d_in[5];

    int n = in_sizes[0] / DDIM;                 // 8192
    if (n > NTOK) n = NTOK;

    float* out = (float*)d_out;

    // Optional concatenated tail outputs: out(N*D), expert_ids(2N), gate(2N), group_idx(N)
    size_t need = (size_t)n * DDIM + 5 * (size_t)n;
    float* o_eid  = nullptr;
    float* o_gate = nullptr;
    float* o_grp  = nullptr;
    if ((size_t)out_size >= need) {
        o_eid  = out + (size_t)n * DDIM;
        o_gate = o_eid + 2 * (size_t)n;
        o_grp  = o_gate + 2 * (size_t)n;
    }

    init_kernel<<<1, 128>>>();
    routing_kernel<<<(n + 7) / 8, 256>>>(h, Wg, bg, Wloc, o_eid, o_gate, o_grp, n);
    prefix_kernel<<<1, 32>>>();
    scatter_kernel<<<(n + 255) / 256, 256>>>(n);
    // slot 0 (top-1 experts): disjoint token rows -> plain writes cover all of out
    expert_kernel<0><<<512, 256>>>(h, W1, W2, out, 0);
    // slot 1 (top-2 experts): disjoint token rows -> non-atomic accumulate
    expert_kernel<1><<<512, 256>>>(h, W1, W2, out, 1);
}